// round 9
// baseline (speedup 1.0000x reference)
#include <cuda_runtime.h>
#include <cuda_bf16.h>

// Problem constants (match reference)
#define BB   64
#define CC   2
#define LL   64
#define NBIN 16
#define NVOX (LL*LL*LL)        // 262144
#define NPAIR (BB*CC)          // 128
#define NDENSE 25              // only ax,az in 0..4 ever occur
#define DSTRIDE 32             // padded partial stride per block
#define EPSV 1e-5f

// tan^2(22a degrees), a = 1..4
#define T1Q 0.16323719f
#define T2Q 0.93255481f
#define T3Q 5.0446812f
#define T4Q 820.03500f

#define SPLIT 8                        // blocks per (b,c) pair
#define CHUNK (NVOX / SPLIT)           // 32768 elements
#define BTHREADS 256

// ---------------------------------------------------------------------------
// COMPILE-TIME bin table (f32 threshold arithmetic identical to the validated
// runtime builder; IEEE f32 in constexpr == runtime FMUL/FSETP -> bit-identical).
// ---------------------------------------------------------------------------
struct BinTable { alignas(16) unsigned char b[NVOX]; };

static constexpr BinTable make_bins() {
    BinTable t{};
    for (int i = 0; i < LL; i++) {
        float fi = (float)i;
        float ii = fi * fi;
        float a1 = ii * T1Q, a2 = ii * T2Q, a3 = ii * T3Q, a4 = ii * T4Q;
        for (int j = 0; j < LL; j++) {
            float fj = (float)j;
            float jj = fj * fj;
            float ij = ii + jj;
            float z1 = ij * T1Q, z2 = ij * T2Q, z3 = ij * T3Q, z4 = ij * T4Q;
            for (int k = 0; k < LL; k++) {
                float fk = (float)k;
                float kk = fk * fk;
                float jk = jj + kk;
                int ax = (jk >= a1) + (jk >= a2) + (jk >= a3) + (jk >= a4);
                int az = (kk >= z1) + (kk >= z2) + (kk >= z3) + (kk >= z4);
                t.b[(i << 12) | (j << 6) | k] = (unsigned char)(ax * 5 + az);
            }
        }
    }
    return t;
}

__device__ constexpr BinTable g_btab = make_bins();

// Per-block partial sums. Slots 25..31 of each DSTRIDE row are NEVER written:
// static zero-init makes them permanently 0, which kernel C exploits to
// vectorize its reduction with float4 over the bin dimension.
__device__ float g_partial[NPAIR * SPLIT * DSTRIDE];   // 128 KB

// ---------------------------------------------------------------------------
// Kernel B: streaming weighted histogram, fully BRANCHLESS hot loop.
//   - per-thread private histogram column: hist[bin*256 + t] (bank = t mod 32,
//     conflict-free for any cross-lane bin pattern)
//   - 8 elements/thread-iter: 2x LDG.128 (__ldcs) + 1x LDG.64 of bin bytes
//   - mag via s * rsqrtf(max(s,0.5)): exact for s>=1 (integer radii), and the
//     single s=0 voxel yields mag=0 exactly; ~2ulp rsqrt error elsewhere
//   - SPLIT=8 -> 1024 CTAs = one wave at 8 CTA/SM smem occupancy
//   - flush: tree-reduce + 25 plain stores to this block's private slot
// ---------------------------------------------------------------------------
__global__ __launch_bounds__(BTHREADS) void accumulate_kernel(const float* __restrict__ x) {
    __shared__ float hist[NDENSE * BTHREADS];     // 25.6 KB
    const int t = threadIdx.x;
    #pragma unroll
    for (int i = 0; i < NDENSE; i++) hist[i * BTHREADS + t] = 0.0f;
    float* __restrict__ h = hist + t;

    const int pair  = blockIdx.x >> 3;            // b*C + c
    const int part  = blockIdx.x & (SPLIT - 1);
    const int vbase = part * CHUNK;
    const float* __restrict__ xp = x + (size_t)pair * NVOX + vbase;
    const unsigned char* __restrict__ bp = g_btab.b + vbase;

    // CHUNK/(256*8) = 16 iterations
    #pragma unroll 4
    for (int off = t * 8; off < CHUNK; off += BTHREADS * 8) {
        float4 xa = __ldcs(reinterpret_cast<const float4*>(xp + off));
        float4 xb = __ldcs(reinterpret_cast<const float4*>(xp + off + 4));
        uint2  bq = *reinterpret_cast<const uint2*>(bp + off);

        int v = vbase + off;                      // off%8==0 -> k..k+7 in-row
        float fi = (float)(v >> 12);
        float fj = (float)((v >> 6) & 63);
        float fk = (float)(v & 63);
        float s2 = fi*fi + fj*fj;
        float f1 = fk + 1.0f, f2 = fk + 2.0f, f3 = fk + 3.0f;
        float f4 = fk + 4.0f, f5 = fk + 5.0f, f6 = fk + 6.0f, f7 = fk + 7.0f;
        float s0q = fmaf(fk, fk, s2), s1q = fmaf(f1, f1, s2);
        float s2q = fmaf(f2, f2, s2), s3q = fmaf(f3, f3, s2);
        float s4q = fmaf(f4, f4, s2), s5q = fmaf(f5, f5, s2);
        float s6q = fmaf(f6, f6, s2), s7q = fmaf(f7, f7, s2);
        float m0 = s0q * rsqrtf(fmaxf(s0q, 0.5f));
        float m1 = s1q * rsqrtf(fmaxf(s1q, 0.5f));
        float m2 = s2q * rsqrtf(fmaxf(s2q, 0.5f));
        float m3 = s3q * rsqrtf(fmaxf(s3q, 0.5f));
        float m4 = s4q * rsqrtf(fmaxf(s4q, 0.5f));
        float m5 = s5q * rsqrtf(fmaxf(s5q, 0.5f));
        float m6 = s6q * rsqrtf(fmaxf(s6q, 0.5f));
        float m7 = s7q * rsqrtf(fmaxf(s7q, 0.5f));

        h[(( bq.x        & 0xffu) << 8)] += xa.x * m0;
        h[(((bq.x >>  8) & 0xffu) << 8)] += xa.y * m1;
        h[(((bq.x >> 16) & 0xffu) << 8)] += xa.z * m2;
        h[(( bq.x >> 24         ) << 8)] += xa.w * m3;
        h[(( bq.y        & 0xffu) << 8)] += xb.x * m4;
        h[(((bq.y >>  8) & 0xffu) << 8)] += xb.y * m5;
        h[(((bq.y >> 16) & 0xffu) << 8)] += xb.z * m6;
        h[(( bq.y >> 24         ) << 8)] += xb.w * m7;
    }

    __syncthreads();

    const int warp = t >> 5, lane = t & 31;
    const unsigned full = 0xffffffffu;
    for (int bin = warp; bin < NDENSE; bin += 8) {
        const float* row = &hist[bin * BTHREADS];
        float s = 0.0f;
        #pragma unroll
        for (int j = 0; j < 8; j++) s += row[lane + 32*j];
        #pragma unroll
        for (int d = 16; d; d >>= 1) s += __shfl_down_sync(full, s, d);
        if (lane == 0) g_partial[blockIdx.x * DSTRIDE + bin] = s;
    }
}

// ---------------------------------------------------------------------------
// Kernel C: per-channel group norm. 32 blocks (16 segments x 2 channels).
// Phase 1: cooperative float4 reduction of the 8 per-split partials into a
//          shared dense[64*28] array (pads are statically zero).
// Phase 2: stats over exactly 1792 = 7*256 shared entries; the 192 zero-pads
//          are compensated in the analytic zero-bin variance term.
// Phase 3: this block writes its disjoint 1024-element output slice from smem.
// ---------------------------------------------------------------------------
#define CSEG 16                        // output segments per channel
#define DPAD 28                        // dense row stride (25 bins + 3 zero pads)

__global__ __launch_bounds__(256) void gn_kernel(const float* __restrict__ gamma,
                                                 const float* __restrict__ beta,
                                                 float* __restrict__ out) {
    const int c   = blockIdx.x & 1;
    const int seg = blockIdx.x >> 1;
    const int t = threadIdx.x;
    const int lane = t & 31, warp = t >> 5;
    const unsigned full = 0xffffffffu;

    __shared__ float dense[BB * DPAD];  // 1792 floats
    __shared__ float red[8];
    __shared__ float s_mean, s_rs;

    // Phase 1: reduce 8 splits, float4 over bins (d-quads 0..6 cover 0..27)
    for (int n = t; n < BB * 7; n += 256) {
        int b = n / 7, dq = n - b * 7;
        const float4* p = reinterpret_cast<const float4*>(
            &g_partial[((b * CC + c) * SPLIT) * DSTRIDE + dq * 4]);
        float4 s = p[0];
        #pragma unroll
        for (int q = 1; q < SPLIT; q++) {
            float4 v = p[q * (DSTRIDE / 4)];
            s.x += v.x; s.y += v.y; s.z += v.z; s.w += v.w;
        }
        *reinterpret_cast<float4*>(&dense[b * DPAD + dq * 4]) = s;
    }
    __syncthreads();

    // Phase 2: stats over 1792 shared entries (192 are zero pads)
    float vals[7];
    float sum = 0.0f;
    #pragma unroll
    for (int i = 0; i < 7; i++) {
        vals[i] = dense[i * 256 + t];
        sum += vals[i];
    }
    #pragma unroll
    for (int d = 16; d; d >>= 1) sum += __shfl_down_sync(full, sum, d);
    if (lane == 0) red[warp] = sum;
    __syncthreads();
    if (t == 0) {
        float tot = 0.0f;
        #pragma unroll
        for (int w = 0; w < 8; w++) tot += red[w];
        s_mean = tot * (1.0f / (BB * NBIN * NBIN));
    }
    __syncthreads();
    float mean = s_mean;

    float vs = 0.0f;
    #pragma unroll
    for (int i = 0; i < 7; i++) {
        float d = vals[i] - mean;
        vs = fmaf(d, d, vs);
    }
    #pragma unroll
    for (int d = 16; d; d >>= 1) vs += __shfl_down_sync(full, vs, d);
    __syncthreads();
    if (lane == 0) red[warp] = vs;
    __syncthreads();
    if (t == 0) {
        float tot = 0.0f;
        #pragma unroll
        for (int w = 0; w < 8; w++) tot += red[w];
        // remaining zero bins beyond the 1792 already counted in the loop
        tot += (float)(BB * NBIN * NBIN - BB * DPAD) * s_mean * s_mean;
        float var = tot * (1.0f / (BB * NBIN * NBIN));
        s_rs = rsqrtf(var + EPSV);
    }
    __syncthreads();
    float rs = s_rs;
    float ga = gamma[c], be = beta[c];

    // Phase 3: outputs [seg*1024, (seg+1)*1024) of channel c
    {
        int idx = seg * 1024 + t;                 // 4 iters of 256
        #pragma unroll
        for (int i = 0; i < 4; i++, idx += 256) {
            int b = idx >> 8, s = idx & 255;
            int ax = s >> 4, az = s & 15;
            float g = 0.0f;
            if (ax < 5 && az < 5)
                g = dense[b * DPAD + ax * 5 + az];
            out[(b * CC + c) * 256 + s] = (g - mean) * rs * ga + be;
        }
    }
}

// ---------------------------------------------------------------------------
extern "C" void kernel_launch(void* const* d_in, const int* in_sizes, int n_in,
                              void* d_out, int out_size) {
    const float* x     = (const float*)d_in[0];   // [64, 2*64^3]
    const float* gamma = (const float*)d_in[1];   // [2]
    const float* beta  = (const float*)d_in[2];   // [2]
    float* out = (float*)d_out;                   // [64,2,16,16] f32

    accumulate_kernel<<<NPAIR * SPLIT, BTHREADS>>>(x);
    gn_kernel<<<CC * CSEG, 256>>>(gamma, beta, out);
}

// round 10
// speedup vs baseline: 1.1308x; 1.1308x over previous
#include <cuda_runtime.h>
#include <cuda_bf16.h>

// Problem constants (match reference)
#define BB   64
#define CC   2
#define LL   64
#define NBIN 16
#define NVOX (LL*LL*LL)        // 262144
#define NPAIR (BB*CC)          // 128
#define NDENSE 25              // only ax,az in 0..4 ever occur
#define DSTRIDE 32             // padded partial stride per block
#define EPSV 1e-5f

// tan^2(22a degrees), a = 1..4
#define T1Q 0.16323719f
#define T2Q 0.93255481f
#define T3Q 5.0446812f
#define T4Q 820.03500f

#define SPLIT 4                        // blocks per (b,c) pair
#define NBLOCKS (NPAIR * SPLIT)        // 512 CTAs: co-resident at >=4 CTA/SM
#define CHUNK (NVOX / SPLIT)           // 65536 elements
#define BTHREADS 256
#define CSEG 16                        // output segments per channel (32 epi blocks)
#define DPAD 28                        // dense row stride (25 bins + 3 zero pads)

// ---------------------------------------------------------------------------
// COMPILE-TIME bin table (f32 threshold arithmetic identical to the validated
// runtime builder; IEEE f32 in constexpr == runtime FMUL/FSETP -> bit-identical).
// ---------------------------------------------------------------------------
struct BinTable { alignas(16) unsigned char b[NVOX]; };

static constexpr BinTable make_bins() {
    BinTable t{};
    for (int i = 0; i < LL; i++) {
        float fi = (float)i;
        float ii = fi * fi;
        float a1 = ii * T1Q, a2 = ii * T2Q, a3 = ii * T3Q, a4 = ii * T4Q;
        for (int j = 0; j < LL; j++) {
            float fj = (float)j;
            float jj = fj * fj;
            float ij = ii + jj;
            float z1 = ij * T1Q, z2 = ij * T2Q, z3 = ij * T3Q, z4 = ij * T4Q;
            for (int k = 0; k < LL; k++) {
                float fk = (float)k;
                float kk = fk * fk;
                float jk = jj + kk;
                int ax = (jk >= a1) + (jk >= a2) + (jk >= a3) + (jk >= a4);
                int az = (kk >= z1) + (kk >= z2) + (kk >= z3) + (kk >= z4);
                t.b[(i << 12) | (j << 6) | k] = (unsigned char)(ax * 5 + az);
            }
        }
    }
    return t;
}

__device__ constexpr BinTable g_btab = make_bins();

// Per-block partial sums. Slots 25..31 of each DSTRIDE row are NEVER written:
// static zero-init keeps them 0 forever, enabling float4 reduction over bins.
__device__ float g_partial[NBLOCKS * DSTRIDE];

// Grid-barrier counters (reset in-kernel each launch -> graph-replay safe)
__device__ unsigned g_arrived = 0;     // accumulate-phase arrivals (target 512)
__device__ unsigned g_epidone = 0;     // epilogue completions      (target 32)

// ---------------------------------------------------------------------------
// ONE fused kernel.
//  Phase 1 (all 512 CTAs): branchless streaming weighted histogram
//    - per-thread private histogram column hist[bin*256+t] (bank = t mod 32)
//    - 8 elems/thread-iter: 2x LDG.128 (__ldcs) + 1x LDG.64 bin bytes
//    - mag via s*rsqrtf(max(s,0.5)): exact for integer radii >=1; s=0 -> 0
//    - flush: tree-reduce, plain stores to this CTA's private partial slot
//  Grid barrier: membar.gpu + counter; all 512 CTAs are co-resident
//    (launch_bounds(256,4): regs<=64, smem 25.6KB -> >=4 CTA/SM -> 592 slots)
//  Phase 2 (CTAs 0..31): group-norm epilogue straight out of L2-hot partials;
//    block 0 resets both counters after all 32 epilogue CTAs signal done.
// ---------------------------------------------------------------------------
__global__ void __launch_bounds__(BTHREADS, 4)
fused_kernel(const float* __restrict__ x,
             const float* __restrict__ gamma,
             const float* __restrict__ beta,
             float* __restrict__ out) {
    __shared__ float hist[NDENSE * BTHREADS];     // 25.6 KB (reused by epilogue)
    const int t = threadIdx.x;
    const int bid = blockIdx.x;
    #pragma unroll
    for (int i = 0; i < NDENSE; i++) hist[i * BTHREADS + t] = 0.0f;
    float* __restrict__ h = hist + t;

    const int pair  = bid >> 2;                   // b*C + c
    const int part  = bid & (SPLIT - 1);
    const int vbase = part * CHUNK;
    const float* __restrict__ xp = x + (size_t)pair * NVOX + vbase;
    const unsigned char* __restrict__ bp = g_btab.b + vbase;

    // CHUNK/(256*8) = 32 iterations
    #pragma unroll 4
    for (int off = t * 8; off < CHUNK; off += BTHREADS * 8) {
        float4 xa = __ldcs(reinterpret_cast<const float4*>(xp + off));
        float4 xb = __ldcs(reinterpret_cast<const float4*>(xp + off + 4));
        uint2  bq = *reinterpret_cast<const uint2*>(bp + off);

        int v = vbase + off;                      // off%8==0 -> k..k+7 in-row
        float fi = (float)(v >> 12);
        float fj = (float)((v >> 6) & 63);
        float fk = (float)(v & 63);
        float s2 = fi*fi + fj*fj;
        float f1 = fk + 1.0f, f2 = fk + 2.0f, f3 = fk + 3.0f;
        float f4 = fk + 4.0f, f5 = fk + 5.0f, f6 = fk + 6.0f, f7 = fk + 7.0f;
        float s0q = fmaf(fk, fk, s2), s1q = fmaf(f1, f1, s2);
        float s2q = fmaf(f2, f2, s2), s3q = fmaf(f3, f3, s2);
        float s4q = fmaf(f4, f4, s2), s5q = fmaf(f5, f5, s2);
        float s6q = fmaf(f6, f6, s2), s7q = fmaf(f7, f7, s2);
        float m0 = s0q * rsqrtf(fmaxf(s0q, 0.5f));
        float m1 = s1q * rsqrtf(fmaxf(s1q, 0.5f));
        float m2 = s2q * rsqrtf(fmaxf(s2q, 0.5f));
        float m3 = s3q * rsqrtf(fmaxf(s3q, 0.5f));
        float m4 = s4q * rsqrtf(fmaxf(s4q, 0.5f));
        float m5 = s5q * rsqrtf(fmaxf(s5q, 0.5f));
        float m6 = s6q * rsqrtf(fmaxf(s6q, 0.5f));
        float m7 = s7q * rsqrtf(fmaxf(s7q, 0.5f));

        h[(( bq.x        & 0xffu) << 8)] += xa.x * m0;
        h[(((bq.x >>  8) & 0xffu) << 8)] += xa.y * m1;
        h[(((bq.x >> 16) & 0xffu) << 8)] += xa.z * m2;
        h[(( bq.x >> 24         ) << 8)] += xa.w * m3;
        h[(( bq.y        & 0xffu) << 8)] += xb.x * m4;
        h[(((bq.y >>  8) & 0xffu) << 8)] += xb.y * m5;
        h[(((bq.y >> 16) & 0xffu) << 8)] += xb.z * m6;
        h[(( bq.y >> 24         ) << 8)] += xb.w * m7;
    }

    __syncthreads();

    // Flush 25 bin totals to this block's private partial slot
    const int warp = t >> 5, lane = t & 31;
    const unsigned full = 0xffffffffu;
    for (int bin = warp; bin < NDENSE; bin += 8) {
        const float* row = &hist[bin * BTHREADS];
        float s = 0.0f;
        #pragma unroll
        for (int j = 0; j < 8; j++) s += row[lane + 32*j];
        #pragma unroll
        for (int d = 16; d; d >>= 1) s += __shfl_down_sync(full, s, d);
        if (lane == 0) g_partial[bid * DSTRIDE + bin] = s;
    }
    __threadfence();                   // order this thread's STGs device-wide
    __syncthreads();
    if (t == 0) atomicAdd(&g_arrived, 1u);

    // ---- epilogue: only CTAs 0..31 (all 512 CTAs are co-resident) ----
    if (bid >= CC * CSEG) return;

    if (t == 0) {
        while (*((volatile unsigned*)&g_arrived) != NBLOCKS) __nanosleep(40);
        __threadfence();               // acquire: order partial loads after flag
    }
    __syncthreads();

    const int c   = bid & 1;
    const int seg = bid >> 1;

    // reuse hist smem: dense[0..1791], red[1792..1799]
    float* dense = hist;
    float* red   = hist + BB * DPAD;
    __shared__ float s_mean, s_rs;

    // Phase 1: reduce 4 splits, float4 over bins (d-quads 0..6 cover 0..27)
    for (int n = t; n < BB * 7; n += BTHREADS) {
        int b = n / 7, dq = n - b * 7;
        const float4* p = reinterpret_cast<const float4*>(
            &g_partial[((b * CC + c) * SPLIT) * DSTRIDE + dq * 4]);
        float4 s = p[0];
        #pragma unroll
        for (int q = 1; q < SPLIT; q++) {
            float4 v = p[q * (DSTRIDE / 4)];
            s.x += v.x; s.y += v.y; s.z += v.z; s.w += v.w;
        }
        *reinterpret_cast<float4*>(&dense[b * DPAD + dq * 4]) = s;
    }
    __syncthreads();

    // Phase 2: stats over 1792 shared entries (192 are zero pads)
    float vals[7];
    float sum = 0.0f;
    #pragma unroll
    for (int i = 0; i < 7; i++) {
        vals[i] = dense[i * BTHREADS + t];
        sum += vals[i];
    }
    #pragma unroll
    for (int d = 16; d; d >>= 1) sum += __shfl_down_sync(full, sum, d);
    if (lane == 0) red[warp] = sum;
    __syncthreads();
    if (t == 0) {
        float tot = 0.0f;
        #pragma unroll
        for (int w = 0; w < 8; w++) tot += red[w];
        s_mean = tot * (1.0f / (BB * NBIN * NBIN));
    }
    __syncthreads();
    float mean = s_mean;

    float vs = 0.0f;
    #pragma unroll
    for (int i = 0; i < 7; i++) {
        float d = vals[i] - mean;
        vs = fmaf(d, d, vs);
    }
    #pragma unroll
    for (int d = 16; d; d >>= 1) vs += __shfl_down_sync(full, vs, d);
    __syncthreads();
    if (lane == 0) red[warp] = vs;
    __syncthreads();
    if (t == 0) {
        float tot = 0.0f;
        #pragma unroll
        for (int w = 0; w < 8; w++) tot += red[w];
        tot += (float)(BB * NBIN * NBIN - BB * DPAD) * s_mean * s_mean;
        float var = tot * (1.0f / (BB * NBIN * NBIN));
        s_rs = rsqrtf(var + EPSV);
    }
    __syncthreads();
    float rs = s_rs;
    float ga = gamma[c], be = beta[c];

    // Phase 3: outputs [seg*1024, (seg+1)*1024) of channel c
    {
        int idx = seg * 1024 + t;                 // 4 iters of 256
        #pragma unroll
        for (int i = 0; i < 4; i++, idx += 256) {
            int b = idx >> 8, s = idx & 255;
            int ax = s >> 4, az = s & 15;
            float g = 0.0f;
            if (ax < 5 && az < 5)
                g = dense[b * DPAD + ax * 5 + az];
            out[(b * CC + c) * 256 + s] = (g - mean) * rs * ga + be;
        }
    }

    // ---- counter reset handshake (graph-replay safety) ----
    __syncthreads();
    if (t == 0) {
        __threadfence();
        atomicAdd(&g_epidone, 1u);
        if (bid == 0) {
            while (*((volatile unsigned*)&g_epidone) != CC * CSEG) __nanosleep(40);
            *((volatile unsigned*)&g_arrived) = 0u;
            *((volatile unsigned*)&g_epidone) = 0u;
        }
    }
}

// ---------------------------------------------------------------------------
extern "C" void kernel_launch(void* const* d_in, const int* in_sizes, int n_in,
                              void* d_out, int out_size) {
    const float* x     = (const float*)d_in[0];   // [64, 2*64^3]
    const float* gamma = (const float*)d_in[1];   // [2]
    const float* beta  = (const float*)d_in[2];   // [2]
    float* out = (float*)d_out;                   // [64,2,16,16] f32

    fused_kernel<<<NBLOCKS, BTHREADS>>>(x, gamma, beta, out);
}